// round 1
// baseline (speedup 1.0000x reference)
#include <cuda_runtime.h>
#include <math.h>

#define NB   2
#define NS   2048
#define ND   1024
#define NH   16
#define NDK  64
#define NBH  (NB*NH)

// Scratch (allocation-free rule: __device__ globals)
__device__ float g_Q[NBH*NS*NDK];
__device__ float g_K[NBH*NS*NDK];
__device__ float g_V[NBH*NS*NDK];
__device__ float g_attn[NB*NS*ND];

// ---------------------------------------------------------------------------
// GEMM: C = A (MxK, row-major) * B^T (NxK, row-major)
// MODE 0: C[m*N+n] = acc        (output projection -> d_out)
// MODE 1: scatter into g_Q/g_K/g_V (QKV projection; n = q*1024 + h*64 + kd)
// Tiles: 128x128x16, 256 threads, 8x8 per thread.
// ---------------------------------------------------------------------------
template<int MODE>
__global__ void __launch_bounds__(256, 1)
gemm_nt_kernel(const float* __restrict__ A, const float* __restrict__ Bm,
               float* __restrict__ C, int M, int N, int K)
{
    __shared__ float As[16][128];
    __shared__ float Bs[16][128];

    const int tid = threadIdx.x;
    const int tx = tid & 15;       // 0..15 -> n sub-block
    const int ty = tid >> 4;       // 0..15 -> m sub-block
    const int m0 = blockIdx.y * 128;
    const int n0 = blockIdx.x * 128;

    float acc[8][8];
    #pragma unroll
    for (int i = 0; i < 8; i++)
        #pragma unroll
        for (int j = 0; j < 8; j++) acc[i][j] = 0.f;

    for (int k0 = 0; k0 < K; k0 += 16) {
        // stage A tile transposed: As[k][m]
        #pragma unroll
        for (int v = 0; v < 2; v++) {
            int e = tid + v * 256;          // float4 index, 512 total
            int row = e >> 2, c4 = e & 3;
            float4 f = *(const float4*)&A[(size_t)(m0 + row) * K + k0 + c4 * 4];
            As[c4*4+0][row] = f.x; As[c4*4+1][row] = f.y;
            As[c4*4+2][row] = f.z; As[c4*4+3][row] = f.w;
        }
        // stage B tile transposed: Bs[k][n]
        #pragma unroll
        for (int v = 0; v < 2; v++) {
            int e = tid + v * 256;
            int row = e >> 2, c4 = e & 3;
            float4 f = *(const float4*)&Bm[(size_t)(n0 + row) * K + k0 + c4 * 4];
            Bs[c4*4+0][row] = f.x; Bs[c4*4+1][row] = f.y;
            Bs[c4*4+2][row] = f.z; Bs[c4*4+3][row] = f.w;
        }
        __syncthreads();

        #pragma unroll
        for (int kk = 0; kk < 16; kk++) {
            float a[8], b[8];
            *(float4*)&a[0] = *(const float4*)&As[kk][ty*8];
            *(float4*)&a[4] = *(const float4*)&As[kk][ty*8+4];
            *(float4*)&b[0] = *(const float4*)&Bs[kk][tx*8];
            *(float4*)&b[4] = *(const float4*)&Bs[kk][tx*8+4];
            #pragma unroll
            for (int i = 0; i < 8; i++)
                #pragma unroll
                for (int j = 0; j < 8; j++)
                    acc[i][j] += a[i] * b[j];
        }
        __syncthreads();
    }

    if (MODE == 0) {
        #pragma unroll
        for (int i = 0; i < 8; i++) {
            size_t m = m0 + ty*8 + i;
            #pragma unroll
            for (int j4 = 0; j4 < 8; j4 += 4) {
                float4 r = make_float4(acc[i][j4], acc[i][j4+1], acc[i][j4+2], acc[i][j4+3]);
                *(float4*)&C[m * (size_t)N + n0 + tx*8 + j4] = r;
            }
        }
    } else {
        // n = q*1024 + h*64 + kd   (q in {0,1,2}: Q,K,V)
        #pragma unroll
        for (int i = 0; i < 8; i++) {
            int m = m0 + ty*8 + i;
            int b = m >> 11;            // / NS
            int s = m & (NS - 1);
            #pragma unroll
            for (int j4 = 0; j4 < 8; j4 += 4) {
                int n  = n0 + tx*8 + j4;
                int q  = n >> 10;
                int h  = (n >> 6) & (NH - 1);
                int kd = n & (NDK - 1);
                float* dst = (q == 0) ? g_Q : (q == 1) ? g_K : g_V;
                size_t off = ((size_t)(b*NH + h) * NS + s) * NDK + kd;
                float4 r = make_float4(acc[i][j4], acc[i][j4+1], acc[i][j4+2], acc[i][j4+3]);
                *(float4*)&dst[off] = r;
            }
        }
    }
}

// ---------------------------------------------------------------------------
// RoPE applied in-place to g_Q and g_K.
// idx bits: [t(1)][bh(5)][s(11)][pair(5)]
// ---------------------------------------------------------------------------
__global__ void rope_kernel(const int* __restrict__ pos)
{
    int idx = blockIdx.x * blockDim.x + threadIdx.x;
    int pr  = idx & 31;
    int s   = (idx >> 5) & (NS - 1);
    int rest = idx >> 16;
    int bh  = rest & (NBH - 1);
    int t   = rest >> 5;

    float p = (float)pos[s];
    // theta = p / 10000^(2*pr/64)
    float denom = powf(10000.f, (float)(2 * pr) / 64.f);
    float th = p / denom;
    float c = cosf(th), si = sinf(th);

    float* ptr = t ? g_K : g_Q;
    size_t base = ((size_t)bh * NS + s) * NDK + pr * 2;
    float x0 = ptr[base], x1 = ptr[base + 1];
    ptr[base]     = x0 * c - x1 * si;
    ptr[base + 1] = x1 * c + x0 * si;
}

// ---------------------------------------------------------------------------
// Causal flash attention, fp32.
// Block = 128 threads handles 64 queries of one (b,h). 64-key tiles.
// Thread grid: ty=tid>>3 (16) -> 4 q-rows each; tx=tid&7 (8) -> 8 cols each.
// Smem (dynamic): Qs[d][q], Ks[d][k], Vs[k][d], Ps[q][k], stride 68.
// ---------------------------------------------------------------------------
#define AST 68
#define ATT_SMEM (4 * 64 * AST * 4)

__global__ void __launch_bounds__(128, 1)
attn_kernel()
{
    extern __shared__ float sm[];
    float* Qs = sm;                 // [64 d][AST] transposed, scaled by 0.125
    float* Ks = sm + 64 * AST;      // [64 d][AST] transposed
    float* Vs = sm + 2 * 64 * AST;  // [64 k][AST]
    float* Ps = sm + 3 * 64 * AST;  // [64 q][AST]

    const int tid = threadIdx.x;
    const int tx = tid & 7;
    const int ty = tid >> 3;
    const int qt = blockIdx.x;      // 0..31
    const int bh = blockIdx.y;      // 0..31
    const int q0 = qt * 64;

    const float* Qp = g_Q + (size_t)bh * NS * NDK;
    const float* Kp = g_K + (size_t)bh * NS * NDK;
    const float* Vp = g_V + (size_t)bh * NS * NDK;

    // Load Q tile (transposed, pre-scaled by 1/sqrt(dk))
    #pragma unroll
    for (int v = 0; v < 8; v++) {
        int e = tid + v * 128;      // float4 index, 1024 total
        int row = e >> 4, c4 = e & 15;
        float4 f = *(const float4*)&Qp[(size_t)(q0 + row) * NDK + c4 * 4];
        Qs[(c4*4+0)*AST + row] = f.x * 0.125f;
        Qs[(c4*4+1)*AST + row] = f.y * 0.125f;
        Qs[(c4*4+2)*AST + row] = f.z * 0.125f;
        Qs[(c4*4+3)*AST + row] = f.w * 0.125f;
    }

    float m_i[4], l_i[4], o[4][8];
    #pragma unroll
    for (int i = 0; i < 4; i++) {
        m_i[i] = -1e30f; l_i[i] = 0.f;
        #pragma unroll
        for (int j = 0; j < 8; j++) o[i][j] = 0.f;
    }

    for (int kt = 0; kt <= qt; kt++) {
        const int k0 = kt * 64;
        // stage K (transposed) and V (direct)
        #pragma unroll
        for (int v = 0; v < 8; v++) {
            int e = tid + v * 128;
            int row = e >> 4, c4 = e & 15;
            float4 f = *(const float4*)&Kp[(size_t)(k0 + row) * NDK + c4 * 4];
            Ks[(c4*4+0)*AST + row] = f.x;
            Ks[(c4*4+1)*AST + row] = f.y;
            Ks[(c4*4+2)*AST + row] = f.z;
            Ks[(c4*4+3)*AST + row] = f.w;
            float4 g = *(const float4*)&Vp[(size_t)(k0 + row) * NDK + c4 * 4];
            *(float4*)&Vs[row * AST + c4 * 4] = g;
        }
        __syncthreads();

        // S = Q K^T (scaled)
        float sc[4][8];
        #pragma unroll
        for (int i = 0; i < 4; i++)
            #pragma unroll
            for (int j = 0; j < 8; j++) sc[i][j] = 0.f;

        #pragma unroll 8
        for (int d = 0; d < 64; d++) {
            float a[4], b[8];
            *(float4*)&a[0] = *(const float4*)&Qs[d * AST + ty * 4];
            *(float4*)&b[0] = *(const float4*)&Ks[d * AST + tx * 8];
            *(float4*)&b[4] = *(const float4*)&Ks[d * AST + tx * 8 + 4];
            #pragma unroll
            for (int i = 0; i < 4; i++)
                #pragma unroll
                for (int j = 0; j < 8; j++)
                    sc[i][j] += a[i] * b[j];
        }

        if (kt == qt) {
            #pragma unroll
            for (int i = 0; i < 4; i++) {
                int qi = q0 + ty * 4 + i;
                #pragma unroll
                for (int j = 0; j < 8; j++)
                    if (k0 + tx * 8 + j > qi) sc[i][j] = -1e30f;
            }
        }

        // online softmax per row; groups of 8 lanes (same ty) reduce via shfl
        #pragma unroll
        for (int i = 0; i < 4; i++) {
            float rm = sc[i][0];
            #pragma unroll
            for (int j = 1; j < 8; j++) rm = fmaxf(rm, sc[i][j]);
            rm = fmaxf(rm, __shfl_xor_sync(0xffffffffu, rm, 1));
            rm = fmaxf(rm, __shfl_xor_sync(0xffffffffu, rm, 2));
            rm = fmaxf(rm, __shfl_xor_sync(0xffffffffu, rm, 4));
            float mn = fmaxf(m_i[i], rm);
            float scale = __expf(m_i[i] - mn);
            m_i[i] = mn;
            float rs = 0.f;
            #pragma unroll
            for (int j = 0; j < 8; j++) {
                float pv = __expf(sc[i][j] - mn);
                sc[i][j] = pv;
                rs += pv;
            }
            rs += __shfl_xor_sync(0xffffffffu, rs, 1);
            rs += __shfl_xor_sync(0xffffffffu, rs, 2);
            rs += __shfl_xor_sync(0xffffffffu, rs, 4);
            l_i[i] = l_i[i] * scale + rs;
            #pragma unroll
            for (int j = 0; j < 8; j++) o[i][j] *= scale;
        }

        // stage P: Ps[q][k]
        #pragma unroll
        for (int i = 0; i < 4; i++)
            #pragma unroll
            for (int j = 0; j < 8; j++)
                Ps[(ty * 4 + i) * AST + tx * 8 + j] = sc[i][j];
        __syncthreads();

        // O += P V
        #pragma unroll 4
        for (int kk = 0; kk < 64; kk++) {
            float a[4], b[8];
            #pragma unroll
            for (int i = 0; i < 4; i++) a[i] = Ps[(ty * 4 + i) * AST + kk];
            *(float4*)&b[0] = *(const float4*)&Vs[kk * AST + tx * 8];
            *(float4*)&b[4] = *(const float4*)&Vs[kk * AST + tx * 8 + 4];
            #pragma unroll
            for (int i = 0; i < 4; i++)
                #pragma unroll
                for (int j = 0; j < 8; j++)
                    o[i][j] += a[i] * b[j];
        }
        __syncthreads();
    }

    // write to g_attn[b][s][h*64 + d]
    const int b = bh >> 4;
    const int h = bh & (NH - 1);
    #pragma unroll
    for (int i = 0; i < 4; i++) {
        float inv = 1.f / l_i[i];
        int q = q0 + ty * 4 + i;
        size_t off = ((size_t)b * NS + q) * ND + h * NDK + tx * 8;
        float4 r0 = make_float4(o[i][0]*inv, o[i][1]*inv, o[i][2]*inv, o[i][3]*inv);
        float4 r1 = make_float4(o[i][4]*inv, o[i][5]*inv, o[i][6]*inv, o[i][7]*inv);
        *(float4*)&g_attn[off]     = r0;
        *(float4*)&g_attn[off + 4] = r1;
    }
}

// ---------------------------------------------------------------------------
extern "C" void kernel_launch(void* const* d_in, const int* in_sizes, int n_in,
                              void* d_out, int out_size)
{
    const float* x   = (const float*)d_in[0];
    const int*   pos = (const int*)d_in[1];
    const float* w   = (const float*)d_in[2];
    const float* wo  = (const float*)d_in[3];
    float* out = (float*)d_out;

    (void)in_sizes; (void)n_in; (void)out_size;

    float* attn_ptr = nullptr;
    cudaGetSymbolAddress((void**)&attn_ptr, g_attn);

    // 1) QKV projection: M=4096, N=3072, K=1024 -> scatter to g_Q/g_K/g_V
    {
        dim3 grid(3072 / 128, 4096 / 128);
        gemm_nt_kernel<1><<<grid, 256>>>(x, w, nullptr, NB * NS, 3 * NH * NDK, ND);
    }

    // 2) RoPE on Q and K
    {
        int total = 2 * NBH * NS * (NDK / 2);
        rope_kernel<<<total / 256, 256>>>(pos);
    }

    // 3) Causal flash attention
    {
        cudaFuncSetAttribute(attn_kernel,
                             cudaFuncAttributeMaxDynamicSharedMemorySize, ATT_SMEM);
        dim3 grid(NS / 64, NBH);
        attn_kernel<<<grid, 128, ATT_SMEM>>>();
    }

    // 4) Output projection: M=4096, N=1024, K=1024 -> d_out
    {
        dim3 grid(1024 / 128, 4096 / 128);
        gemm_nt_kernel<0><<<grid, 256>>>(attn_ptr, wo, out, NB * NS, ND, ND);
    }
}

// round 3
// speedup vs baseline: 2.6047x; 2.6047x over previous
#include <cuda_runtime.h>
#include <cuda_bf16.h>
#include <cuda_fp16.h>
#include <math.h>
#include <stdint.h>

#define NB   2
#define NS   2048
#define ND   1024
#define NH   16
#define NDK  64
#define NBH  (NB*NH)

// ---------------- scratch (allocation-free rule: __device__ globals) -------
__device__ float g_Q[NBH*NS*NDK];
__device__ float g_K[NBH*NS*NDK];
__device__ float g_V[NBH*NS*NDK];
__device__ float g_attn[NB*NS*ND];

__device__ __nv_bfloat16 g_xhi[NB*NS*ND],  g_xlo[NB*NS*ND];
__device__ __nv_bfloat16 g_whi[3*ND*ND],   g_wlo[3*ND*ND];
__device__ __nv_bfloat16 g_wohi[ND*ND],    g_wolo[ND*ND];
__device__ __nv_bfloat16 g_ahi[NB*NS*ND],  g_alo[NB*NS*ND];

// ---------------- warp-mma helpers (sm_80+ ISA; compiles for plain sm_103) --
__device__ __forceinline__ uint32_t smem_u32(const void* p) {
    uint32_t a;
    asm("{ .reg .u64 t; cvta.to.shared.u64 t, %1; cvt.u32.u64 %0, t; }"
        : "=r"(a) : "l"(p));
    return a;
}
__device__ __forceinline__ void ldsm_x4(uint32_t r[4], uint32_t addr) {
    asm volatile("ldmatrix.sync.aligned.m8n8.x4.shared.b16 {%0,%1,%2,%3}, [%4];"
        : "=r"(r[0]), "=r"(r[1]), "=r"(r[2]), "=r"(r[3]) : "r"(addr));
}
__device__ __forceinline__ void ldsm_x2(uint32_t r[2], uint32_t addr) {
    asm volatile("ldmatrix.sync.aligned.m8n8.x2.shared.b16 {%0,%1}, [%2];"
        : "=r"(r[0]), "=r"(r[1]) : "r"(addr));
}
__device__ __forceinline__ void ldsm_x2_trans(uint32_t r[2], uint32_t addr) {
    asm volatile("ldmatrix.sync.aligned.m8n8.x2.trans.shared.b16 {%0,%1}, [%2];"
        : "=r"(r[0]), "=r"(r[1]) : "r"(addr));
}
__device__ __forceinline__ void mma_bf16(float c[4], const uint32_t a[4],
                                         const uint32_t b[2]) {
    asm volatile(
        "mma.sync.aligned.m16n8k16.row.col.f32.bf16.bf16.f32 "
        "{%0,%1,%2,%3}, {%4,%5,%6,%7}, {%8,%9}, {%0,%1,%2,%3};"
        : "+f"(c[0]), "+f"(c[1]), "+f"(c[2]), "+f"(c[3])
        : "r"(a[0]), "r"(a[1]), "r"(a[2]), "r"(a[3]), "r"(b[0]), "r"(b[1]));
}
__device__ __forceinline__ void mma_f16(float c[4], const uint32_t a[4],
                                        const uint32_t b[2]) {
    asm volatile(
        "mma.sync.aligned.m16n8k16.row.col.f32.f16.f16.f32 "
        "{%0,%1,%2,%3}, {%4,%5,%6,%7}, {%8,%9}, {%0,%1,%2,%3};"
        : "+f"(c[0]), "+f"(c[1]), "+f"(c[2]), "+f"(c[3])
        : "r"(a[0]), "r"(a[1]), "r"(a[2]), "r"(a[3]), "r"(b[0]), "r"(b[1]));
}
__device__ __forceinline__ uint32_t pack_f16x2(float lo, float hi) {
    uint32_t r;
    asm("cvt.rn.f16x2.f32 %0, %1, %2;" : "=r"(r) : "f"(hi), "f"(lo));
    return r;
}

// ---------------------------------------------------------------------------
// fp32 -> (bf16 hi, bf16 lo) split. 4 elements / thread.
// ---------------------------------------------------------------------------
__global__ void split_kernel(const float* __restrict__ src,
                             __nv_bfloat16* __restrict__ hi,
                             __nv_bfloat16* __restrict__ lo)
{
    int i = blockIdx.x * blockDim.x + threadIdx.x;
    float4 v = *(const float4*)&src[(size_t)i * 4];
    __nv_bfloat16 hx = __float2bfloat16(v.x);
    __nv_bfloat16 hy = __float2bfloat16(v.y);
    __nv_bfloat16 hz = __float2bfloat16(v.z);
    __nv_bfloat16 hw = __float2bfloat16(v.w);
    __nv_bfloat16 lx = __float2bfloat16(v.x - __bfloat162float(hx));
    __nv_bfloat16 ly = __float2bfloat16(v.y - __bfloat162float(hy));
    __nv_bfloat16 lz = __float2bfloat16(v.z - __bfloat162float(hz));
    __nv_bfloat16 lw = __float2bfloat16(v.w - __bfloat162float(hw));
    ((__nv_bfloat162*)hi)[i*2]   = __nv_bfloat162(hx, hy);
    ((__nv_bfloat162*)hi)[i*2+1] = __nv_bfloat162(hz, hw);
    ((__nv_bfloat162*)lo)[i*2]   = __nv_bfloat162(lx, ly);
    ((__nv_bfloat162*)lo)[i*2+1] = __nv_bfloat162(lz, lw);
}

// ---------------------------------------------------------------------------
// bf16x3 GEMM via mma.sync: C = A * B^T, fp32 acc.
// C = Ahi*Bhi + Alo*Bhi + Ahi*Blo   (3 K-passes)
// Tile 128x128, 256 threads (8 warps = 2m x 4n, warp tile 64x32).
// K-chunk 32, double-buffered smem with register prefetch.
// MODE 0: C[m*N+n]; MODE 1: scatter into g_Q/g_K/g_V.
// ---------------------------------------------------------------------------
#define GPAD 40   // smem row stride in bf16 elems (80B: conflict-free ldmatrix)

template<int MODE>
__global__ void __launch_bounds__(256, 1)
gemm_mma_kernel(const __nv_bfloat16* __restrict__ Ahi,
                const __nv_bfloat16* __restrict__ Alo,
                const __nv_bfloat16* __restrict__ Bhi,
                const __nv_bfloat16* __restrict__ Blo,
                float* __restrict__ C, int M, int N, int K)
{
    __shared__ __align__(16) __nv_bfloat16 sA[2][128 * GPAD];
    __shared__ __align__(16) __nv_bfloat16 sB[2][128 * GPAD];

    const int tid = threadIdx.x;
    const int wid = tid >> 5;
    const int l   = tid & 31;
    const int wm  = (wid & 1) * 64;    // warp m-offset
    const int wn  = (wid >> 1) * 32;   // warp n-offset
    const int m0 = blockIdx.y * 128;
    const int n0 = blockIdx.x * 128;

    const int segs = K / 32;           // chunks per pass
    const int nc = 3 * segs;

    float c[4][4][4];
    #pragma unroll
    for (int mt = 0; mt < 4; mt++)
        #pragma unroll
        for (int nt = 0; nt < 4; nt++)
            #pragma unroll
            for (int j = 0; j < 4; j++) c[mt][nt][j] = 0.f;

    // per-thread load coords: 512 uint4 per tile, 2 per thread
    const int r0 = (tid) >> 2,        cu0 = (tid) & 3;
    const int r1 = (tid + 256) >> 2,  cu1 = (tid + 256) & 3;

    uint4 ra0, ra1, rb0, rb1;

    auto load_chunk = [&](int cidx) {
        int seg = cidx / segs;
        int kc = (cidx - seg * segs) * 32;
        const __nv_bfloat16* As = (seg == 1) ? Alo : Ahi;
        const __nv_bfloat16* Bs = (seg == 2) ? Blo : Bhi;
        ra0 = *(const uint4*)(As + (size_t)(m0 + r0) * K + kc + cu0 * 8);
        ra1 = *(const uint4*)(As + (size_t)(m0 + r1) * K + kc + cu1 * 8);
        rb0 = *(const uint4*)(Bs + (size_t)(n0 + r0) * K + kc + cu0 * 8);
        rb1 = *(const uint4*)(Bs + (size_t)(n0 + r1) * K + kc + cu1 * 8);
    };
    auto store_chunk = [&](int buf) {
        *(uint4*)&sA[buf][r0 * GPAD + cu0 * 8] = ra0;
        *(uint4*)&sA[buf][r1 * GPAD + cu1 * 8] = ra1;
        *(uint4*)&sB[buf][r0 * GPAD + cu0 * 8] = rb0;
        *(uint4*)&sB[buf][r1 * GPAD + cu1 * 8] = rb1;
    };

    load_chunk(0);
    store_chunk(0);
    __syncthreads();

    const uint32_t sAb = smem_u32(&sA[0][0]);
    const uint32_t sBb = smem_u32(&sB[0][0]);
    const uint32_t bufA = 128 * GPAD * 2;   // bytes per buffer

    for (int cidx = 0; cidx < nc; cidx++) {
        if (cidx + 1 < nc) load_chunk(cidx + 1);
        int buf = cidx & 1;
        uint32_t baseA = sAb + buf * bufA;
        uint32_t baseB = sBb + buf * bufA;

        #pragma unroll
        for (int ks = 0; ks < 2; ks++) {
            uint32_t af[4][4];
            #pragma unroll
            for (int mt = 0; mt < 4; mt++) {
                uint32_t addr = baseA +
                    ((wm + mt * 16 + (l & 15)) * GPAD + ks * 16 + ((l >> 4) & 1) * 8) * 2;
                ldsm_x4(af[mt], addr);
            }
            #pragma unroll
            for (int nt = 0; nt < 4; nt++) {
                uint32_t bf2[2];
                uint32_t addr = baseB +
                    ((wn + nt * 8 + (l & 7)) * GPAD + ks * 16 + ((l & 8) ? 8 : 0)) * 2;
                ldsm_x2(bf2, addr);
                #pragma unroll
                for (int mt = 0; mt < 4; mt++)
                    mma_bf16(c[mt][nt], af[mt], bf2);
            }
        }
        __syncthreads();
        if (cidx + 1 < nc) {
            store_chunk((cidx + 1) & 1);
            __syncthreads();
        }
    }

    // epilogue: c-frag (mt,nt): rows m0+wm+mt*16+(l/4)+{0,8}, cols n0+wn+nt*8+2*(l%4)+{0,1}
    #pragma unroll
    for (int mt = 0; mt < 4; mt++) {
        #pragma unroll
        for (int half = 0; half < 2; half++) {
            int m = m0 + wm + mt * 16 + (l >> 2) + half * 8;
            #pragma unroll
            for (int nt = 0; nt < 4; nt++) {
                int n = n0 + wn + nt * 8 + 2 * (l & 3);
                float2 val = make_float2(c[mt][nt][half*2], c[mt][nt][half*2+1]);
                if (MODE == 0) {
                    *(float2*)&C[(size_t)m * N + n] = val;
                } else {
                    int b = m >> 11;
                    int s = m & (NS - 1);
                    int q  = n >> 10;
                    int h  = (n >> 6) & (NH - 1);
                    int kd = n & (NDK - 1);
                    float* dst = (q == 0) ? g_Q : (q == 1) ? g_K : g_V;
                    *(float2*)&dst[((size_t)(b * NH + h) * NS + s) * NDK + kd] = val;
                }
            }
        }
    }
}

// ---------------------------------------------------------------------------
// RoPE applied in-place to g_Q and g_K.
// ---------------------------------------------------------------------------
__global__ void rope_kernel(const int* __restrict__ pos)
{
    int idx = blockIdx.x * blockDim.x + threadIdx.x;
    int pr  = idx & 31;
    int s   = (idx >> 5) & (NS - 1);
    int rest = idx >> 16;
    int bh  = rest & (NBH - 1);
    int t   = rest >> 5;

    float p = (float)pos[s];
    float denom = powf(10000.f, (float)(2 * pr) / 64.f);
    float th = p / denom;
    float c = cosf(th), si = sinf(th);

    float* ptr = t ? g_K : g_Q;
    size_t base = ((size_t)bh * NS + s) * NDK + pr * 2;
    float x0 = ptr[base], x1 = ptr[base + 1];
    ptr[base]     = x0 * c - x1 * si;
    ptr[base + 1] = x1 * c + x0 * si;
}

// ---------------------------------------------------------------------------
// Causal flash attention via mma.sync fp16 (fp32 softmax).
// Block: 256 thr (8 warps), q-tile 128 (16 rows / warp), k-tile 64.
// ---------------------------------------------------------------------------
#define APAD 72   // fp16 row stride (144B)

__global__ void __launch_bounds__(256, 1)
attn_mma_kernel()
{
    __shared__ __align__(16) __half Qs[128 * APAD];
    __shared__ __align__(16) __half Ks[64 * APAD];
    __shared__ __align__(16) __half Vs[64 * APAD];

    const int tid = threadIdx.x;
    const int wid = tid >> 5;
    const int l   = tid & 31;
    const int qb  = blockIdx.x;
    const int bh  = blockIdx.y;
    const int q0  = qb * 128;

    const float* Qp = g_Q + (size_t)bh * NS * NDK;
    const float* Kp = g_K + (size_t)bh * NS * NDK;
    const float* Vp = g_V + (size_t)bh * NS * NDK;

    // load Q tile (scaled by 1/sqrt(dk))
    #pragma unroll
    for (int v = 0; v < 32; v++) {
        int e = tid + v * 256;
        int row = e >> 6, col = e & 63;
        Qs[row * APAD + col] = __float2half(Qp[(size_t)(q0 + row) * NDK + col] * 0.125f);
    }
    __syncthreads();

    // Q a-frags held in registers for whole kernel
    uint32_t aq[4][4];
    const uint32_t Qsb = smem_u32(Qs);
    #pragma unroll
    for (int ks = 0; ks < 4; ks++) {
        uint32_t addr = Qsb +
            ((wid * 16 + (l & 15)) * APAD + ks * 16 + ((l >> 4) & 1) * 8) * 2;
        ldsm_x4(aq[ks], addr);
    }
    __syncthreads();  // Qs no longer needed by loads... (kept resident)

    float m0r = -1e30f, m1r = -1e30f, l0r = 0.f, l1r = 0.f;
    float o[8][4];
    #pragma unroll
    for (int dt = 0; dt < 8; dt++)
        #pragma unroll
        for (int j = 0; j < 4; j++) o[dt][j] = 0.f;

    const uint32_t Ksb = smem_u32(Ks);
    const uint32_t Vsb = smem_u32(Vs);
    const int nkt = 2 * qb + 2;

    for (int kt = 0; kt < nkt; kt++) {
        const int k0 = kt * 64;
        // stage K,V (fp32 -> fp16)
        #pragma unroll
        for (int v = 0; v < 16; v++) {
            int e = tid + v * 256;
            int row = e >> 6, col = e & 63;
            Ks[row * APAD + col] = __float2half(Kp[(size_t)(k0 + row) * NDK + col]);
            Vs[row * APAD + col] = __float2half(Vp[(size_t)(k0 + row) * NDK + col]);
        }
        __syncthreads();

        if (k0 <= q0 + wid * 16 + 15) {   // warp has at least one unmasked row
            // S = Q K^T
            float s[8][4];
            #pragma unroll
            for (int nt = 0; nt < 8; nt++)
                #pragma unroll
                for (int j = 0; j < 4; j++) s[nt][j] = 0.f;

            #pragma unroll
            for (int ks = 0; ks < 4; ks++) {
                #pragma unroll
                for (int nt = 0; nt < 8; nt++) {
                    uint32_t bk[2];
                    uint32_t addr = Ksb +
                        ((nt * 8 + (l & 7)) * APAD + ks * 16 + ((l & 8) ? 8 : 0)) * 2;
                    ldsm_x2(bk, addr);
                    mma_f16(s[nt], aq[ks], bk);
                }
            }

            // causal mask (only needed near diagonal)
            const int row0 = q0 + wid * 16 + (l >> 2);
            if (k0 + 63 > q0 + wid * 16) {
                #pragma unroll
                for (int nt = 0; nt < 8; nt++) {
                    int col = k0 + nt * 8 + 2 * (l & 3);
                    if (col     > row0)     s[nt][0] = -1e30f;
                    if (col + 1 > row0)     s[nt][1] = -1e30f;
                    if (col     > row0 + 8) s[nt][2] = -1e30f;
                    if (col + 1 > row0 + 8) s[nt][3] = -1e30f;
                }
            }

            // online softmax (two rows per thread)
            float mt0 = -1e30f, mt1 = -1e30f;
            #pragma unroll
            for (int nt = 0; nt < 8; nt++) {
                mt0 = fmaxf(mt0, fmaxf(s[nt][0], s[nt][1]));
                mt1 = fmaxf(mt1, fmaxf(s[nt][2], s[nt][3]));
            }
            mt0 = fmaxf(mt0, __shfl_xor_sync(0xffffffffu, mt0, 1));
            mt0 = fmaxf(mt0, __shfl_xor_sync(0xffffffffu, mt0, 2));
            mt1 = fmaxf(mt1, __shfl_xor_sync(0xffffffffu, mt1, 1));
            mt1 = fmaxf(mt1, __shfl_xor_sync(0xffffffffu, mt1, 2));

            float mn0 = fmaxf(m0r, mt0), mn1 = fmaxf(m1r, mt1);
            float sc0 = __expf(m0r - mn0), sc1 = __expf(m1r - mn1);
            m0r = mn0; m1r = mn1;

            float rs0 = 0.f, rs1 = 0.f;
            #pragma unroll
            for (int nt = 0; nt < 8; nt++) {
                s[nt][0] = __expf(s[nt][0] - mn0); rs0 += s[nt][0];
                s[nt][1] = __expf(s[nt][1] - mn0); rs0 += s[nt][1];
                s[nt][2] = __expf(s[nt][2] - mn1); rs1 += s[nt][2];
                s[nt][3] = __expf(s[nt][3] - mn1); rs1 += s[nt][3];
            }
            rs0 += __shfl_xor_sync(0xffffffffu, rs0, 1);
            rs0 += __shfl_xor_sync(0xffffffffu, rs0, 2);
            rs1 += __shfl_xor_sync(0xffffffffu, rs1, 1);
            rs1 += __shfl_xor_sync(0xffffffffu, rs1, 2);
            l0r = l0r * sc0 + rs0;
            l1r = l1r * sc1 + rs1;

            #pragma unroll
            for (int dt = 0; dt < 8; dt++) {
                o[dt][0] *= sc0; o[dt][1] *= sc0;
                o[dt][2] *= sc1; o[dt][3] *= sc1;
            }

            // O += P V   (P from S regs: C-frag -> A-frag repack)
            #pragma unroll
            for (int kp = 0; kp < 4; kp++) {
                uint32_t ap[4];
                ap[0] = pack_f16x2(s[2*kp][0],   s[2*kp][1]);
                ap[1] = pack_f16x2(s[2*kp][2],   s[2*kp][3]);
                ap[2] = pack_f16x2(s[2*kp+1][0], s[2*kp+1][1]);
                ap[3] = pack_f16x2(s[2*kp+1][2], s[2*kp+1][3]);
                #pragma unroll
                for (int dt = 0; dt < 8; dt++) {
                    uint32_t bv[2];
                    uint32_t addr = Vsb +
                        ((kp * 16 + (l & 15)) * APAD + dt * 8) * 2;
                    ldsm_x2_trans(bv, addr);
                    mma_f16(o[dt], ap, bv);
                }
            }
        }
        __syncthreads();
    }

    // write O (normalized) to g_attn[b][s][h*64+d]
    const int b = bh >> 4;
    const int h = bh & (NH - 1);
    float inv0 = 1.f / l0r, inv1 = 1.f / l1r;
    int rr0 = q0 + wid * 16 + (l >> 2);
    #pragma unroll
    for (int dt = 0; dt < 8; dt++) {
        int d = h * NDK + dt * 8 + 2 * (l & 3);
        *(float2*)&g_attn[((size_t)b * NS + rr0) * ND + d] =
            make_float2(o[dt][0] * inv0, o[dt][1] * inv0);
        *(float2*)&g_attn[((size_t)b * NS + rr0 + 8) * ND + d] =
            make_float2(o[dt][2] * inv1, o[dt][3] * inv1);
    }
}

// ---------------------------------------------------------------------------
extern "C" void kernel_launch(void* const* d_in, const int* in_sizes, int n_in,
                              void* d_out, int out_size)
{
    const float* x   = (const float*)d_in[0];
    const int*   pos = (const int*)d_in[1];
    const float* w   = (const float*)d_in[2];
    const float* wo  = (const float*)d_in[3];
    float* out = (float*)d_out;
    (void)in_sizes; (void)n_in; (void)out_size;

    float* attn_ptr = nullptr;
    cudaGetSymbolAddress((void**)&attn_ptr, g_attn);
    __nv_bfloat16 *xhi, *xlo, *whi, *wlo, *wohi, *wolo, *ahi, *alo;
    cudaGetSymbolAddress((void**)&xhi, g_xhi);
    cudaGetSymbolAddress((void**)&xlo, g_xlo);
    cudaGetSymbolAddress((void**)&whi, g_whi);
    cudaGetSymbolAddress((void**)&wlo, g_wlo);
    cudaGetSymbolAddress((void**)&wohi, g_wohi);
    cudaGetSymbolAddress((void**)&wolo, g_wolo);
    cudaGetSymbolAddress((void**)&ahi, g_ahi);
    cudaGetSymbolAddress((void**)&alo, g_alo);

    // 0) split inputs to bf16 hi/lo
    split_kernel<<<(NB*NS*ND/4)/256, 256>>>(x, xhi, xlo);
    split_kernel<<<(3*ND*ND/4)/256, 256>>>(w, whi, wlo);
    split_kernel<<<(ND*ND/4)/256, 256>>>(wo, wohi, wolo);

    // 1) QKV projection: M=4096, N=3072, K=1024 -> scatter g_Q/g_K/g_V
    {
        dim3 grid(3072 / 128, 4096 / 128);
        gemm_mma_kernel<1><<<grid, 256>>>(xhi, xlo, whi, wlo,
                                          nullptr, NB * NS, 3 * ND, ND);
    }

    // 2) RoPE on Q and K
    {
        int total = 2 * NBH * NS * (NDK / 2);
        rope_kernel<<<total / 256, 256>>>(pos);
    }

    // 3) Causal flash attention (fp16 mma, fp32 softmax)
    {
        dim3 grid(NS / 128, NBH);
        attn_mma_kernel<<<grid, 256>>>();
    }

    // 4) split attention output, then output projection
    split_kernel<<<(NB*NS*ND/4)/256, 256>>>(attn_ptr, ahi, alo);
    {
        dim3 grid(1024 / 128, 4096 / 128);
        gemm_mma_kernel<0><<<grid, 256>>>(ahi, alo, wohi, wolo,
                                          out, NB * NS, ND, ND);
    }
}